// round 1
// baseline (speedup 1.0000x reference)
#include <cuda_runtime.h>
#include <math.h>

#define D_MODEL 1024
#define DFF     4096
#define SEQ     2048
#define BATCH   2
#define NTOK    (SEQ*BATCH)      // 4096
#define NHEADS  16
#define HDIM    64

// ---------------- scratch (device globals: allocation-free rule) ----------------
__device__ float g_ln [NTOK*D_MODEL];
__device__ float g_q  [NTOK*D_MODEL];
__device__ float g_k  [NTOK*D_MODEL];
__device__ float g_v  [NTOK*D_MODEL];
__device__ float g_ctx[NTOK*D_MODEL];
__device__ float g_h  [NTOK*D_MODEL];
__device__ float g_f1 [NTOK*(size_t)DFF];

// ---------------- layernorm: one block per row, 256 threads ----------------
__global__ void __launch_bounds__(256) ln_kernel(const float* __restrict__ in,
                                                 const float* __restrict__ gamma,
                                                 const float* __restrict__ beta,
                                                 float* __restrict__ out)
{
    int row = blockIdx.x;
    const float* x = in + (size_t)row * D_MODEL;
    int t = threadIdx.x;
    float v[4];
    float s = 0.f;
#pragma unroll
    for (int i = 0; i < 4; i++) { v[i] = x[i*256 + t]; s += v[i]; }

    __shared__ float red[8];
    __shared__ float bcast;
#pragma unroll
    for (int o = 16; o > 0; o >>= 1) s += __shfl_xor_sync(0xffffffffu, s, o);
    if ((t & 31) == 0) red[t >> 5] = s;
    __syncthreads();
    if (t < 32) {
        float r = (t < 8) ? red[t] : 0.f;
#pragma unroll
        for (int o = 4; o > 0; o >>= 1) r += __shfl_xor_sync(0xffffffffu, r, o);
        if (t == 0) bcast = r;
    }
    __syncthreads();
    float mean = bcast * (1.f / D_MODEL);

    float s2 = 0.f;
#pragma unroll
    for (int i = 0; i < 4; i++) { float d = v[i] - mean; s2 += d*d; }
#pragma unroll
    for (int o = 16; o > 0; o >>= 1) s2 += __shfl_xor_sync(0xffffffffu, s2, o);
    __syncthreads();                       // red reuse
    if ((t & 31) == 0) red[t >> 5] = s2;
    __syncthreads();
    if (t < 32) {
        float r = (t < 8) ? red[t] : 0.f;
#pragma unroll
        for (int o = 4; o > 0; o >>= 1) r += __shfl_xor_sync(0xffffffffu, r, o);
        if (t == 0) bcast = r;
    }
    __syncthreads();
    float rstd = rsqrtf(bcast * (1.f / D_MODEL) + 1e-5f);

#pragma unroll
    for (int i = 0; i < 4; i++) {
        int d = i*256 + t;
        out[(size_t)row * D_MODEL + d] = gamma[d] * (v[i] - mean) * rstd + beta[d];
    }
}

// ---------------- SGEMM: 128x128x8 tile, 256 threads, 8x8 per thread ----------------
// C[M,N] = A[M,K] @ B[K,N]  (+bias[n]) (gelu) (+res[m,n])
// Requires M%128==0, N%128==0, K%8==0 (true for all shapes here).
template<bool BIAS, bool GELU, bool RES>
__global__ void __launch_bounds__(256) sgemm_kernel(
    const float* __restrict__ A, const float* __restrict__ B,
    const float* __restrict__ bias, const float* __restrict__ res,
    float* __restrict__ C, int M, int N, int K)
{
    __shared__ float As[8][128];
    __shared__ float Bs[8][128];

    int t  = threadIdx.x;
    int tx = t & 15;
    int ty = t >> 4;
    int m0 = blockIdx.y * 128;
    int n0 = blockIdx.x * 128;

    float acc[8][8];
#pragma unroll
    for (int i = 0; i < 8; i++)
#pragma unroll
        for (int j = 0; j < 8; j++) acc[i][j] = 0.f;

    int arow = t >> 1;           // 0..127
    int acol = (t & 1) * 4;      // 0 / 4
    int brow = t >> 5;           // 0..7
    int bcol = (t & 31) * 4;     // 0..124

    const float* Aptr = A + (size_t)(m0 + arow) * K + acol;
    const float* Bptr = B + (size_t)brow * N + n0 + bcol;

    for (int k0 = 0; k0 < K; k0 += 8) {
        float4 a4 = *(const float4*)(Aptr + k0);
        float4 b4 = *(const float4*)(Bptr + (size_t)k0 * N);
        As[acol+0][arow] = a4.x;
        As[acol+1][arow] = a4.y;
        As[acol+2][arow] = a4.z;
        As[acol+3][arow] = a4.w;
        *(float4*)&Bs[brow][bcol] = b4;
        __syncthreads();

#pragma unroll
        for (int kk = 0; kk < 8; kk++) {
            float af[8], bf[8];
#pragma unroll
            for (int i = 0; i < 8; i++) af[i] = As[kk][i*16 + ty];
#pragma unroll
            for (int j = 0; j < 8; j++) bf[j] = Bs[kk][j*16 + tx];
#pragma unroll
            for (int i = 0; i < 8; i++)
#pragma unroll
                for (int j = 0; j < 8; j++)
                    acc[i][j] = fmaf(af[i], bf[j], acc[i][j]);
        }
        __syncthreads();
    }

#pragma unroll
    for (int i = 0; i < 8; i++) {
        int m = m0 + i*16 + ty;
#pragma unroll
        for (int j = 0; j < 8; j++) {
            int n = n0 + j*16 + tx;
            float v = acc[i][j];
            if (BIAS) v += bias[n];
            if (GELU) {
                float xx = v;
                float u = 0.7978845608028654f * (xx + 0.044715f * xx*xx*xx);
                v = 0.5f * xx * (1.f + tanhf(u));
            }
            if (RES) v += res[(size_t)m * N + n];
            C[(size_t)m * N + n] = v;
        }
    }
}

// ---------------- flash attention (fp32), 64-query tiles, causal ----------------
// grid: (SEQ/64, BATCH*NHEADS), 256 threads; dynamic smem 65792 B
__global__ void __launch_bounds__(256) attn_kernel(
    const float* __restrict__ Q, const float* __restrict__ K,
    const float* __restrict__ V, float* __restrict__ O)
{
    extern __shared__ float sm[];
    float* Qs = sm;                 // 64*64
    float* Ks = Qs + 64*64;         // 64*65 (padded: column-ish reads)
    float* Vs = Ks + 64*65;         // 64*64
    float* Ps = Vs + 64*64;         // 64*64
#define QS_(r,c) Qs[(r)*64+(c)]
#define KS_(r,c) Ks[(r)*65+(c)]
#define VS_(r,c) Vs[(r)*64+(c)]
#define PS_(r,c) Ps[(r)*64+(c)]

    int qt = blockIdx.x;
    int bh = blockIdx.y;
    int b  = bh / NHEADS;
    int h  = bh % NHEADS;
    int t  = threadIdx.x;
    int tx = t & 15;
    int ty = t >> 4;

    size_t base = (size_t)b * SEQ * D_MODEL + (size_t)h * HDIM;

    // load Q tile (64 rows x 64 dims)
    for (int idx = t; idx < 1024; idx += 256) {
        int r  = idx >> 4;
        int c4 = (idx & 15) * 4;
        float4 q4 = *(const float4*)(Q + base + (size_t)(qt*64 + r) * D_MODEL + c4);
        QS_(r, c4+0) = q4.x; QS_(r, c4+1) = q4.y;
        QS_(r, c4+2) = q4.z; QS_(r, c4+3) = q4.w;
    }

    float m_i[4], l_i[4], o_acc[4][4];
#pragma unroll
    for (int i = 0; i < 4; i++) {
        m_i[i] = -1e30f; l_i[i] = 0.f;
#pragma unroll
        for (int j = 0; j < 4; j++) o_acc[i][j] = 0.f;
    }
    __syncthreads();

    for (int kt = 0; kt <= qt; kt++) {
        // load K,V tiles
        for (int idx = t; idx < 1024; idx += 256) {
            int r  = idx >> 4;
            int c4 = (idx & 15) * 4;
            size_t g = base + (size_t)(kt*64 + r) * D_MODEL + c4;
            float4 k4 = *(const float4*)(K + g);
            KS_(r, c4+0) = k4.x; KS_(r, c4+1) = k4.y;
            KS_(r, c4+2) = k4.z; KS_(r, c4+3) = k4.w;
            float4 v4 = *(const float4*)(V + g);
            VS_(r, c4+0) = v4.x; VS_(r, c4+1) = v4.y;
            VS_(r, c4+2) = v4.z; VS_(r, c4+3) = v4.w;
        }
        __syncthreads();

        // S = Q K^T (4x4 per thread)
        float s[4][4];
#pragma unroll
        for (int i = 0; i < 4; i++)
#pragma unroll
            for (int j = 0; j < 4; j++) s[i][j] = 0.f;
        for (int k = 0; k < 64; k++) {
            float qf[4], kf[4];
#pragma unroll
            for (int i = 0; i < 4; i++) qf[i] = QS_(4*ty + i, k);
#pragma unroll
            for (int j = 0; j < 4; j++) kf[j] = KS_(4*tx + j, k);
#pragma unroll
            for (int i = 0; i < 4; i++)
#pragma unroll
                for (int j = 0; j < 4; j++)
                    s[i][j] = fmaf(qf[i], kf[j], s[i][j]);
        }

        const float scale = 0.125f;   // 1/sqrt(64)
        if (kt == qt) {
#pragma unroll
            for (int i = 0; i < 4; i++)
#pragma unroll
                for (int j = 0; j < 4; j++) {
                    int qg = 4*ty + i, kg = 4*tx + j;
                    s[i][j] = (kg <= qg) ? s[i][j] * scale : -1e30f;
                }
        } else {
#pragma unroll
            for (int i = 0; i < 4; i++)
#pragma unroll
                for (int j = 0; j < 4; j++) s[i][j] *= scale;
        }

        // online softmax: row stats across the 16 tx lanes
        float alpha[4];
#pragma unroll
        for (int i = 0; i < 4; i++) {
            float mt = fmaxf(fmaxf(s[i][0], s[i][1]), fmaxf(s[i][2], s[i][3]));
#pragma unroll
            for (int o = 8; o > 0; o >>= 1)
                mt = fmaxf(mt, __shfl_xor_sync(0xffffffffu, mt, o));
            float mn = fmaxf(m_i[i], mt);
            alpha[i] = __expf(m_i[i] - mn);
            m_i[i] = mn;
        }
#pragma unroll
        for (int i = 0; i < 4; i++) {
            float rs = 0.f;
#pragma unroll
            for (int j = 0; j < 4; j++) {
                float p = __expf(s[i][j] - m_i[i]);
                PS_(4*ty + i, 4*tx + j) = p;
                rs += p;
            }
#pragma unroll
            for (int o = 8; o > 0; o >>= 1)
                rs += __shfl_xor_sync(0xffffffffu, rs, o);
            l_i[i] = l_i[i] * alpha[i] + rs;
#pragma unroll
            for (int j = 0; j < 4; j++) o_acc[i][j] *= alpha[i];
        }
        __syncthreads();   // Ps visible

        // O += P V
        for (int c = 0; c < 64; c++) {
            float pf[4], vf[4];
#pragma unroll
            for (int i = 0; i < 4; i++) pf[i] = PS_(4*ty + i, c);
#pragma unroll
            for (int j = 0; j < 4; j++) vf[j] = VS_(c, 4*tx + j);
#pragma unroll
            for (int i = 0; i < 4; i++)
#pragma unroll
                for (int j = 0; j < 4; j++)
                    o_acc[i][j] = fmaf(pf[i], vf[j], o_acc[i][j]);
        }
        __syncthreads();   // before Ks/Vs/Ps reuse
    }

#pragma unroll
    for (int i = 0; i < 4; i++) {
        float inv_l = 1.f / l_i[i];
        int q = qt*64 + 4*ty + i;
#pragma unroll
        for (int j = 0; j < 4; j++) {
            O[base + (size_t)q * D_MODEL + 4*tx + j] = o_acc[i][j] * inv_l;
        }
    }
#undef QS_
#undef KS_
#undef VS_
#undef PS_
}

// ---------------- launch ----------------
extern "C" void kernel_launch(void* const* d_in, const int* in_sizes, int n_in,
                              void* d_out, int out_size)
{
    (void)in_sizes; (void)n_in; (void)out_size;
    const float* x  = (const float*)d_in[0];
    const float* Wq = (const float*)d_in[1];
    const float* Wk = (const float*)d_in[2];
    const float* Wv = (const float*)d_in[3];
    const float* Wo = (const float*)d_in[4];
    const float* bo = (const float*)d_in[5];
    const float* W1 = (const float*)d_in[6];
    const float* b1 = (const float*)d_in[7];
    const float* W2 = (const float*)d_in[8];
    const float* b2 = (const float*)d_in[9];
    const float* g1 = (const float*)d_in[10];
    const float* s1 = (const float*)d_in[11];
    const float* g2 = (const float*)d_in[12];
    const float* s2 = (const float*)d_in[13];
    float* out = (float*)d_out;

    float *ln, *q, *k, *v, *ctx, *h, *f1;
    cudaGetSymbolAddress((void**)&ln,  g_ln);
    cudaGetSymbolAddress((void**)&q,   g_q);
    cudaGetSymbolAddress((void**)&k,   g_k);
    cudaGetSymbolAddress((void**)&v,   g_v);
    cudaGetSymbolAddress((void**)&ctx, g_ctx);
    cudaGetSymbolAddress((void**)&h,   g_h);
    cudaGetSymbolAddress((void**)&f1,  g_f1);

    const int ATTN_SMEM = (64*64*3 + 64*65) * 4;   // 65792 B
    cudaFuncSetAttribute(attn_kernel, cudaFuncAttributeMaxDynamicSharedMemorySize, ATTN_SMEM);

    // 1. ln1 = LN(x)
    ln_kernel<<<NTOK, 256>>>(x, g1, s1, ln);
    // 2-4. q/k/v = ln1 @ W{q,k,v}
    sgemm_kernel<false,false,false><<<dim3(D_MODEL/128, NTOK/128), 256>>>(ln, Wq, nullptr, nullptr, q,  NTOK, D_MODEL, D_MODEL);
    sgemm_kernel<false,false,false><<<dim3(D_MODEL/128, NTOK/128), 256>>>(ln, Wk, nullptr, nullptr, k,  NTOK, D_MODEL, D_MODEL);
    sgemm_kernel<false,false,false><<<dim3(D_MODEL/128, NTOK/128), 256>>>(ln, Wv, nullptr, nullptr, v,  NTOK, D_MODEL, D_MODEL);
    // 5. causal attention
    attn_kernel<<<dim3(SEQ/64, BATCH*NHEADS), 256, ATTN_SMEM>>>(q, k, v, ctx);
    // 6. h = x + ctx @ Wo + bo
    sgemm_kernel<true,false,true><<<dim3(D_MODEL/128, NTOK/128), 256>>>(ctx, Wo, bo, x, h, NTOK, D_MODEL, D_MODEL);
    // 7. ln2 = LN(h)
    ln_kernel<<<NTOK, 256>>>(h, g2, s2, ln);
    // 8. f1 = gelu(ln2 @ W1 + b1)
    sgemm_kernel<true,true,false><<<dim3(DFF/128, NTOK/128), 256>>>(ln, W1, b1, nullptr, f1, NTOK, DFF, D_MODEL);
    // 9. out = h + f1 @ W2 + b2
    sgemm_kernel<true,false,true><<<dim3(D_MODEL/128, NTOK/128), 256>>>(f1, W2, b2, h, out, NTOK, D_MODEL, DFF);
}

// round 4
// speedup vs baseline: 2.1156x; 2.1156x over previous
#include <cuda_runtime.h>
#include <cuda_bf16.h>
#include <cstdint>
#include <math.h>

#define D_MODEL 1024
#define DFF     4096
#define SEQ     2048
#define BATCH   2
#define NTOK    (SEQ*BATCH)      // 4096
#define NHEADS  16
#define HDIM    64
#define QKV_W   3072             // fused qkv width

// ---------------- scratch (device globals: allocation-free rule) ----------------
__device__ float g_ln  [NTOK*D_MODEL];
__device__ float g_qkv [NTOK*(size_t)QKV_W];
__device__ float g_ctx [NTOK*D_MODEL];
__device__ float g_h   [NTOK*D_MODEL];
__device__ float g_f1  [NTOK*(size_t)DFF];
__device__ float g_wqkvT[(size_t)QKV_W*D_MODEL];   // [3072,1024]
__device__ float g_woT  [(size_t)D_MODEL*D_MODEL]; // [1024,1024]
__device__ float g_w1T  [(size_t)DFF*D_MODEL];     // [4096,1024]
__device__ float g_w2T  [(size_t)D_MODEL*DFF];     // [1024,4096]

// ================= helpers =================
__device__ __forceinline__ uint32_t smem_u32(const void* p) {
    uint32_t a;
    asm("{ .reg .u64 t; cvta.to.shared.u64 t, %1; cvt.u32.u64 %0, t; }" : "=r"(a) : "l"(p));
    return a;
}

#define LDSM_X4(r0,r1,r2,r3,a) \
    asm volatile("ldmatrix.sync.aligned.m8n8.x4.shared.b16 {%0,%1,%2,%3}, [%4];" \
        : "=r"(r0), "=r"(r1), "=r"(r2), "=r"(r3) : "r"(a))

#define MMA_BF16(c, a, b0, b1) \
    asm volatile("mma.sync.aligned.m16n8k16.row.col.f32.bf16.bf16.f32 " \
        "{%0,%1,%2,%3}, {%4,%5,%6,%7}, {%8,%9}, {%0,%1,%2,%3};" \
        : "+f"((c)[0]), "+f"((c)[1]), "+f"((c)[2]), "+f"((c)[3]) \
        : "r"((a)[0]), "r"((a)[1]), "r"((a)[2]), "r"((a)[3]), "r"(b0), "r"(b1))

__device__ __forceinline__ uint32_t pack_bf2(__nv_bfloat16 a, __nv_bfloat16 b) {
    __nv_bfloat162 t; t.x = a; t.y = b;
    return *(uint32_t*)&t;
}

// ================= weight transpose: in[R,C] -> out[C,R] =================
__global__ void __launch_bounds__(256) transpose_kernel(const float* __restrict__ in,
                                                        float* __restrict__ out, int R, int C)
{
    __shared__ float tile[32][33];
    int tx = threadIdx.x, ty = threadIdx.y;
    int x = blockIdx.x * 32 + tx;
    int y0 = blockIdx.y * 32;
#pragma unroll
    for (int i = ty; i < 32; i += 8)
        tile[i][tx] = in[(size_t)(y0 + i) * C + x];
    __syncthreads();
    int xo = y0 + tx;
    int y1 = blockIdx.x * 32;
#pragma unroll
    for (int i = ty; i < 32; i += 8)
        out[(size_t)(y1 + i) * R + xo] = tile[tx][i];
}

// ================= layernorm =================
__global__ void __launch_bounds__(256) ln_kernel(const float* __restrict__ in,
                                                 const float* __restrict__ gamma,
                                                 const float* __restrict__ beta,
                                                 float* __restrict__ out)
{
    int row = blockIdx.x;
    const float* x = in + (size_t)row * D_MODEL;
    int t = threadIdx.x;
    float v[4];
    float s = 0.f;
#pragma unroll
    for (int i = 0; i < 4; i++) { v[i] = x[i*256 + t]; s += v[i]; }

    __shared__ float red[8];
    __shared__ float bcast;
#pragma unroll
    for (int o = 16; o > 0; o >>= 1) s += __shfl_xor_sync(0xffffffffu, s, o);
    if ((t & 31) == 0) red[t >> 5] = s;
    __syncthreads();
    if (t < 32) {
        float r = (t < 8) ? red[t] : 0.f;
#pragma unroll
        for (int o = 4; o > 0; o >>= 1) r += __shfl_xor_sync(0xffffffffu, r, o);
        if (t == 0) bcast = r;
    }
    __syncthreads();
    float mean = bcast * (1.f / D_MODEL);

    float s2 = 0.f;
#pragma unroll
    for (int i = 0; i < 4; i++) { float d = v[i] - mean; s2 += d*d; }
#pragma unroll
    for (int o = 16; o > 0; o >>= 1) s2 += __shfl_xor_sync(0xffffffffu, s2, o);
    __syncthreads();
    if ((t & 31) == 0) red[t >> 5] = s2;
    __syncthreads();
    if (t < 32) {
        float r = (t < 8) ? red[t] : 0.f;
#pragma unroll
        for (int o = 4; o > 0; o >>= 1) r += __shfl_xor_sync(0xffffffffu, r, o);
        if (t == 0) bcast = r;
    }
    __syncthreads();
    float rstd = rsqrtf(bcast * (1.f / D_MODEL) + 1e-5f);

#pragma unroll
    for (int i = 0; i < 4; i++) {
        int d = i*256 + t;
        out[(size_t)row * D_MODEL + d] = gamma[d] * (v[i] - mean) * rstd + beta[d];
    }
}

// ================= split-bf16 mma.sync GEMM =================
// C[M,N] = A[M,K] @ Bt[N,K]^T  (+bias[n]) (gelu) (+res[m,n])
// CTA tile 128x128, K chunk 32; 8 warps, warp tile 32x64.
// smem per stage: Ah/Al/Bh/Bl each 128 rows x 40 halves (80B stride) = 10240 B
#define ROW_HALVES 40
#define ROW_BYTES  80
#define MAT_BYTES  (128*ROW_BYTES)      // 10240
#define STAGE_BYTES (4*MAT_BYTES)       // 40960
#define GEMM_SMEM  (2*STAGE_BYTES)      // 81920

template<int EPI>   // 0=none, 1=bias+res, 2=bias+gelu
__global__ void __launch_bounds__(256) gemm_mma(
    const float* __restrict__ A, const float* __restrict__ Bt,
    const float* __restrict__ bias, const float* __restrict__ res,
    float* __restrict__ C, int M, int N, int K)
{
    extern __shared__ char dynsm[];
    uint32_t sbase = smem_u32(dynsm);

    int t = threadIdx.x;
    int lane = t & 31, wid = t >> 5;
    int warp_m = wid & 3;        // 0..3  -> 32-row slice
    int warp_n = wid >> 2;       // 0..1  -> 64-col slice
    int m0 = blockIdx.y * 128, n0 = blockIdx.x * 128;
    const int NC = K >> 5;

    const float* Ap = A  + (size_t)m0 * K;
    const float* Bp = Bt + (size_t)n0 * K;

    int lrow  = t >> 3;          // 0..31 base row
    int lcol4 = (t & 7) * 4;     // 0,4,..28

    float acc[2][8][4];
#pragma unroll
    for (int mt = 0; mt < 2; mt++)
#pragma unroll
        for (int nt = 0; nt < 8; nt++)
#pragma unroll
            for (int r = 0; r < 4; r++) acc[mt][nt][r] = 0.f;

    // ---- convert+store one float4 (hi into mat_base, lo into mat_base+MAT_BYTES) ----
    auto sts_pair = [&](uint32_t mat_base, int row, int col4, float4 v) {
        __nv_bfloat16 h0 = __float2bfloat16(v.x);
        __nv_bfloat16 h1 = __float2bfloat16(v.y);
        __nv_bfloat16 h2 = __float2bfloat16(v.z);
        __nv_bfloat16 h3 = __float2bfloat16(v.w);
        __nv_bfloat16 l0 = __float2bfloat16(v.x - __bfloat162float(h0));
        __nv_bfloat16 l1 = __float2bfloat16(v.y - __bfloat162float(h1));
        __nv_bfloat16 l2 = __float2bfloat16(v.z - __bfloat162float(h2));
        __nv_bfloat16 l3 = __float2bfloat16(v.w - __bfloat162float(h3));
        uint32_t ah = mat_base + (uint32_t)(row * ROW_BYTES + col4 * 2);
        asm volatile("st.shared.v2.b32 [%0], {%1, %2};" :: "r"(ah),
                     "r"(pack_bf2(h0,h1)), "r"(pack_bf2(h2,h3)) : "memory");
        asm volatile("st.shared.v2.b32 [%0], {%1, %2};" :: "r"(ah + MAT_BYTES),
                     "r"(pack_bf2(l0,l1)), "r"(pack_bf2(l2,l3)) : "memory");
    };
    // stage layout: [Ah | Al | Bh | Bl], each MAT_BYTES

    auto load_chunk_direct = [&](int k0, int st) {
        uint32_t stb = sbase + (uint32_t)st * STAGE_BYTES;
#pragma unroll
        for (int i = 0; i < 4; i++) {
            int row = lrow + i * 32;
            float4 a4 = *(const float4*)(Ap + (size_t)row * K + k0 + lcol4);
            sts_pair(stb, row, lcol4, a4);
            float4 b4 = *(const float4*)(Bp + (size_t)row * K + k0 + lcol4);
            sts_pair(stb + 2*MAT_BYTES, row, lcol4, b4);
        }
    };

    // ---- compute on a stage ----
    auto compute_stage = [&](int st) {
        uint32_t stb = sbase + (uint32_t)st * STAGE_BYTES;
        uint32_t ah_base = stb;
        uint32_t bh_base = stb + 2*MAT_BYTES;
#pragma unroll
        for (int ks = 0; ks < 2; ks++) {
            // A fragments (hi + lo) for 2 m-tiles
            uint32_t afh[2][4], afl[2][4];
#pragma unroll
            for (int mt = 0; mt < 2; mt++) {
                int row = warp_m * 32 + mt * 16 + (lane & 15);
                int kcol = ks * 16 + (lane >> 4) * 8;
                uint32_t addr = ah_base + (uint32_t)(row * ROW_BYTES + kcol * 2);
                LDSM_X4(afh[mt][0], afh[mt][1], afh[mt][2], afh[mt][3], addr);
                LDSM_X4(afl[mt][0], afl[mt][1], afl[mt][2], afl[mt][3], addr + MAT_BYTES);
            }
#pragma unroll
            for (int np = 0; np < 4; np++) {
                // B fragments for 16 n-cols (2 n-tiles): NON-transposed ldmatrix.
                // lanes 0-7: n 0-7 @k0 | 8-15: n 0-7 @k+8 | 16-23: n 8-15 @k0 | 24-31: n 8-15 @k+8
                int nrow = warp_n * 64 + np * 16 + (lane & 7) + ((lane >> 4) << 3);
                int kcol = ks * 16 + ((lane >> 3) & 1) * 8;
                uint32_t addr = bh_base + (uint32_t)(nrow * ROW_BYTES + kcol * 2);
                uint32_t bfh[4], bfl[4];
                LDSM_X4(bfh[0], bfh[1], bfh[2], bfh[3], addr);
                LDSM_X4(bfl[0], bfl[1], bfl[2], bfl[3], addr + MAT_BYTES);
#pragma unroll
                for (int mt = 0; mt < 2; mt++) {
                    int nt0 = np * 2;
                    MMA_BF16(acc[mt][nt0],   afh[mt], bfh[0], bfh[1]);
                    MMA_BF16(acc[mt][nt0+1], afh[mt], bfh[2], bfh[3]);
                    MMA_BF16(acc[mt][nt0],   afh[mt], bfl[0], bfl[1]);
                    MMA_BF16(acc[mt][nt0+1], afh[mt], bfl[2], bfl[3]);
                    MMA_BF16(acc[mt][nt0],   afl[mt], bfh[0], bfh[1]);
                    MMA_BF16(acc[mt][nt0+1], afl[mt], bfh[2], bfh[3]);
                }
            }
        }
    };

    // ---- pipelined main loop ----
    load_chunk_direct(0, 0);
    __syncthreads();

    for (int c = 0; c < NC; c++) {
        int st = c & 1;
        bool has_next = (c + 1 < NC);
        float4 abuf[4], bbuf[4];
        if (has_next) {
            int k0 = (c + 1) * 32;
#pragma unroll
            for (int i = 0; i < 4; i++) {
                int row = lrow + i * 32;
                abuf[i] = *(const float4*)(Ap + (size_t)row * K + k0 + lcol4);
                bbuf[i] = *(const float4*)(Bp + (size_t)row * K + k0 + lcol4);
            }
        }
        compute_stage(st);
        if (has_next) {
            uint32_t stb = sbase + (uint32_t)(1 - st) * STAGE_BYTES;
#pragma unroll
            for (int i = 0; i < 4; i++) {
                int row = lrow + i * 32;
                sts_pair(stb, row, lcol4, abuf[i]);
                sts_pair(stb + 2*MAT_BYTES, row, lcol4, bbuf[i]);
            }
        }
        __syncthreads();
    }

    // ---- epilogue ----
    int g   = lane >> 2;
    int tig = lane & 3;
#pragma unroll
    for (int mt = 0; mt < 2; mt++) {
#pragma unroll
        for (int nt = 0; nt < 8; nt++) {
            int col = n0 + warp_n * 64 + nt * 8 + 2 * tig;
            int row0 = m0 + warp_m * 32 + mt * 16 + g;
            int row1 = row0 + 8;
            float v00 = acc[mt][nt][0], v01 = acc[mt][nt][1];
            float v10 = acc[mt][nt][2], v11 = acc[mt][nt][3];
            if (EPI != 0) {
                float b0 = bias[col], b1 = bias[col + 1];
                v00 += b0; v01 += b1; v10 += b0; v11 += b1;
            }
            if (EPI == 2) {
                float vv[4] = {v00, v01, v10, v11};
#pragma unroll
                for (int q = 0; q < 4; q++) {
                    float xx = vv[q];
                    float u = 0.7978845608028654f * (xx + 0.044715f * xx * xx * xx);
                    vv[q] = 0.5f * xx * (1.f + tanhf(u));
                }
                v00 = vv[0]; v01 = vv[1]; v10 = vv[2]; v11 = vv[3];
            }
            if (EPI == 1) {
                float2 r0 = *(const float2*)(res + (size_t)row0 * N + col);
                float2 r1 = *(const float2*)(res + (size_t)row1 * N + col);
                v00 += r0.x; v01 += r0.y; v10 += r1.x; v11 += r1.y;
            }
            *(float2*)(C + (size_t)row0 * N + col) = make_float2(v00, v01);
            *(float2*)(C + (size_t)row1 * N + col) = make_float2(v10, v11);
        }
    }
}

// ================= flash attention (fp32), strided qkv input =================
__global__ void __launch_bounds__(256) attn_kernel(
    const float* __restrict__ QKV, float* __restrict__ O)
{
    extern __shared__ float sm[];
    float* Qs = sm;                 // 64*64
    float* Ks = Qs + 64*64;         // 64*65
    float* Vs = Ks + 64*65;         // 64*64
    float* Ps = Vs + 64*64;         // 64*64
#define QS_(r,c) Qs[(r)*64+(c)]
#define KS_(r,c) Ks[(r)*65+(c)]
#define VS_(r,c) Vs[(r)*64+(c)]
#define PS_(r,c) Ps[(r)*64+(c)]

    int qt = blockIdx.x;
    int bh = blockIdx.y;
    int b  = bh / NHEADS;
    int h  = bh % NHEADS;
    int t  = threadIdx.x;
    int tx = t & 15;
    int ty = t >> 4;

    size_t rowbase = (size_t)b * SEQ * QKV_W;
    const float* Qg = QKV + rowbase + h * HDIM;
    const float* Kg = QKV + rowbase + D_MODEL + h * HDIM;
    const float* Vg = QKV + rowbase + 2 * D_MODEL + h * HDIM;

    for (int idx = t; idx < 1024; idx += 256) {
        int r  = idx >> 4;
        int c4 = (idx & 15) * 4;
        float4 q4 = *(const float4*)(Qg + (size_t)(qt*64 + r) * QKV_W + c4);
        QS_(r, c4+0) = q4.x; QS_(r, c4+1) = q4.y;
        QS_(r, c4+2) = q4.z; QS_(r, c4+3) = q4.w;
    }

    float m_i[4], l_i[4], o_acc[4][4];
#pragma unroll
    for (int i = 0; i < 4; i++) {
        m_i[i] = -1e30f; l_i[i] = 0.f;
#pragma unroll
        for (int j = 0; j < 4; j++) o_acc[i][j] = 0.f;
    }
    __syncthreads();

    for (int kt = 0; kt <= qt; kt++) {
        for (int idx = t; idx < 1024; idx += 256) {
            int r  = idx >> 4;
            int c4 = (idx & 15) * 4;
            size_t grow = (size_t)(kt*64 + r) * QKV_W + c4;
            float4 k4 = *(const float4*)(Kg + grow);
            KS_(r, c4+0) = k4.x; KS_(r, c4+1) = k4.y;
            KS_(r, c4+2) = k4.z; KS_(r, c4+3) = k4.w;
            float4 v4 = *(const float4*)(Vg + grow);
            VS_(r, c4+0) = v4.x; VS_(r, c4+1) = v4.y;
            VS_(r, c4+2) = v4.z; VS_(r, c4+3) = v4.w;
        }
        __syncthreads();

        float s[4][4];
#pragma unroll
        for (int i = 0; i < 4; i++)
#pragma unroll
            for (int j = 0; j < 4; j++) s[i][j] = 0.f;
        for (int k = 0; k < 64; k++) {
            float qf[4], kf[4];
#pragma unroll
            for (int i = 0; i < 4; i++) qf[i] = QS_(4*ty + i, k);
#pragma unroll
            for (int j = 0; j < 4; j++) kf[j] = KS_(4*tx + j, k);
#pragma unroll
            for (int i = 0; i < 4; i++)
#pragma unroll
                for (int j = 0; j < 4; j++)
                    s[i][j] = fmaf(qf[i], kf[j], s[i][j]);
        }

        const float scale = 0.125f;
        if (kt == qt) {
#pragma unroll
            for (int i = 0; i < 4; i++)
#pragma unroll
                for (int j = 0; j < 4; j++) {
                    int qg = 4*ty + i, kg = 4*tx + j;
                    s[i][j] = (kg <= qg) ? s[i][j] * scale : -1e30f;
                }
        } else {
#pragma unroll
            for (int i = 0; i < 4; i++)
#pragma unroll
                for (int j = 0; j < 4; j++) s[i][j] *= scale;
        }

        float alpha[4];
#pragma unroll
        for (int i = 0; i < 4; i++) {
            float mt = fmaxf(fmaxf(s[i][0], s[i][1]), fmaxf(s[i][2], s[i][3]));
#pragma unroll
            for (int o = 8; o > 0; o >>= 1)
                mt = fmaxf(mt, __shfl_xor_sync(0xffffffffu, mt, o));
            float mn = fmaxf(m_i[i], mt);
            alpha[i] = __expf(m_i[i] - mn);
            m_i[i] = mn;
        }
#pragma unroll
        for (int i = 0; i < 4; i++) {
            float rs = 0.f;
#pragma unroll
            for (int j = 0; j < 4; j++) {
                float p = __expf(s[i][j] - m_i[i]);
                PS_(4*ty + i, 4*tx + j) = p;
                rs += p;
            }
#pragma unroll
            for (int o = 8; o > 0; o >>= 1)
                rs += __shfl_xor_sync(0xffffffffu, rs, o);
            l_i[i] = l_i[i] * alpha[i] + rs;
#pragma unroll
            for (int j = 0; j < 4; j++) o_acc[i][j] *= alpha[i];
        }
        __syncthreads();

        for (int c = 0; c < 64; c++) {
            float pf[4], vf[4];
#pragma unroll
            for (int i = 0; i < 4; i++) pf[i] = PS_(4*ty + i, c);
#pragma unroll
            for (int j = 0; j < 4; j++) vf[j] = VS_(c, 4*tx + j);
#pragma unroll
            for (int i = 0; i < 4; i++)
#pragma unroll
                for (int j = 0; j < 4; j++)
                    o_acc[i][j] = fmaf(pf[i], vf[j], o_acc[i][j]);
        }
        __syncthreads();
    }

    size_t obase = (size_t)b * SEQ * D_MODEL + (size_t)h * HDIM;
#pragma unroll
    for (int i = 0; i < 4; i++) {
        float inv_l = 1.f / l_i[i];
        int q = qt*64 + 4*ty + i;
#pragma unroll
        for (int j = 0; j < 4; j++) {
            O[obase + (size_t)q * D_MODEL + 4*tx + j] = o_acc[i][j] * inv_l;
        }
    }
#undef QS_
#undef KS_
#undef VS_
#undef PS_
}

// ================= launch =================
extern "C" void kernel_launch(void* const* d_in, const int* in_sizes, int n_in,
                              void* d_out, int out_size)
{
    (void)in_sizes; (void)n_in; (void)out_size;
    const float* x  = (const float*)d_in[0];
    const float* Wq = (const float*)d_in[1];
    const float* Wk = (const float*)d_in[2];
    const float* Wv = (const float*)d_in[3];
    const float* Wo = (const float*)d_in[4];
    const float* bo = (const float*)d_in[5];
    const float* W1 = (const float*)d_in[6];
    const float* b1 = (const float*)d_in[7];
    const float* W2 = (const float*)d_in[8];
    const float* b2 = (const float*)d_in[9];
    const float* g1 = (const float*)d_in[10];
    const float* s1 = (const float*)d_in[11];
    const float* g2 = (const float*)d_in[12];
    const float* s2 = (const float*)d_in[13];
    float* out = (float*)d_out;

    float *ln, *qkv, *ctx, *h, *f1, *wqkvT, *woT, *w1T, *w2T;
    cudaGetSymbolAddress((void**)&ln,    g_ln);
    cudaGetSymbolAddress((void**)&qkv,   g_qkv);
    cudaGetSymbolAddress((void**)&ctx,   g_ctx);
    cudaGetSymbolAddress((void**)&h,     g_h);
    cudaGetSymbolAddress((void**)&f1,    g_f1);
    cudaGetSymbolAddress((void**)&wqkvT, g_wqkvT);
    cudaGetSymbolAddress((void**)&woT,   g_woT);
    cudaGetSymbolAddress((void**)&w1T,   g_w1T);
    cudaGetSymbolAddress((void**)&w2T,   g_w2T);

    cudaFuncSetAttribute(gemm_mma<0>, cudaFuncAttributeMaxDynamicSharedMemorySize, GEMM_SMEM);
    cudaFuncSetAttribute(gemm_mma<1>, cudaFuncAttributeMaxDynamicSharedMemorySize, GEMM_SMEM);
    cudaFuncSetAttribute(gemm_mma<2>, cudaFuncAttributeMaxDynamicSharedMemorySize, GEMM_SMEM);
    const int ATTN_SMEM = (64*64*3 + 64*65) * 4;
    cudaFuncSetAttribute(attn_kernel, cudaFuncAttributeMaxDynamicSharedMemorySize, ATTN_SMEM);

    dim3 tb(32, 8);
    // weight transposes: W[K,N] -> Wt[N,K]
    transpose_kernel<<<dim3(D_MODEL/32, D_MODEL/32), tb>>>(Wq, wqkvT,                        D_MODEL, D_MODEL);
    transpose_kernel<<<dim3(D_MODEL/32, D_MODEL/32), tb>>>(Wk, wqkvT + 1024*(size_t)D_MODEL, D_MODEL, D_MODEL);
    transpose_kernel<<<dim3(D_MODEL/32, D_MODEL/32), tb>>>(Wv, wqkvT + 2048*(size_t)D_MODEL, D_MODEL, D_MODEL);
    transpose_kernel<<<dim3(D_MODEL/32, D_MODEL/32), tb>>>(Wo, woT, D_MODEL, D_MODEL);
    transpose_kernel<<<dim3(DFF/32,     D_MODEL/32), tb>>>(W1, w1T, D_MODEL, DFF);
    transpose_kernel<<<dim3(D_MODEL/32, DFF/32),     tb>>>(W2, w2T, DFF, D_MODEL);

    // 1. ln1 = LN(x)
    ln_kernel<<<NTOK, 256>>>(x, g1, s1, ln);
    // 2. qkv = ln1 @ [Wq|Wk|Wv]
    gemm_mma<0><<<dim3(QKV_W/128, NTOK/128), 256, GEMM_SMEM>>>(ln, wqkvT, nullptr, nullptr, qkv, NTOK, QKV_W, D_MODEL);
    // 3. causal attention
    attn_kernel<<<dim3(SEQ/64, BATCH*NHEADS), 256, ATTN_SMEM>>>(qkv, ctx);
    // 4. h = x + ctx @ Wo + bo
    gemm_mma<1><<<dim3(D_MODEL/128, NTOK/128), 256, GEMM_SMEM>>>(ctx, woT, bo, x, h, NTOK, D_MODEL, D_MODEL);
    // 5. ln2 = LN(h)
    ln_kernel<<<NTOK, 256>>>(h, g2, s2, ln);
    // 6. f1 = gelu(ln2 @ W1 + b1)
    gemm_mma<2><<<dim3(DFF/128, NTOK/128), 256, GEMM_SMEM>>>(ln, w1T, b1, nullptr, f1, NTOK, DFF, D_MODEL);
    // 7. out = h + f1 @ W2 + b2
    gemm_mma<1><<<dim3(D_MODEL/128, NTOK/128), 256, GEMM_SMEM>>>(f1, w2T, b2, h, out, NTOK, D_MODEL, DFF);
}

// round 5
// speedup vs baseline: 2.6745x; 1.2642x over previous
#include <cuda_runtime.h>
#include <cuda_bf16.h>
#include <cstdint>
#include <math.h>

#define D_MODEL 1024
#define DFF     4096
#define SEQ     2048
#define BATCH   2
#define NTOK    (SEQ*BATCH)      // 4096
#define NHEADS  16
#define HDIM    64
#define QKV_W   3072             // fused qkv width

// ---------------- scratch (device globals: allocation-free rule) ----------------
__device__ float g_ln  [NTOK*D_MODEL];
__device__ float g_qkv [NTOK*(size_t)QKV_W];
__device__ float g_ctx [NTOK*D_MODEL];
__device__ float g_h   [NTOK*D_MODEL];
__device__ float g_f1  [NTOK*(size_t)DFF];
__device__ float g_wqkvT[(size_t)QKV_W*D_MODEL];   // [3072,1024]
__device__ float g_woT  [(size_t)D_MODEL*D_MODEL]; // [1024,1024]
__device__ float g_w1T  [(size_t)DFF*D_MODEL];     // [4096,1024]
__device__ float g_w2T  [(size_t)D_MODEL*DFF];     // [1024,4096]

// ================= helpers =================
__device__ __forceinline__ uint32_t smem_u32(const void* p) {
    uint32_t a;
    asm("{ .reg .u64 t; cvta.to.shared.u64 t, %1; cvt.u32.u64 %0, t; }" : "=r"(a) : "l"(p));
    return a;
}

#define LDSM_X4(r0,r1,r2,r3,a) \
    asm volatile("ldmatrix.sync.aligned.m8n8.x4.shared.b16 {%0,%1,%2,%3}, [%4];" \
        : "=r"(r0), "=r"(r1), "=r"(r2), "=r"(r3) : "r"(a))
#define LDSM_X4_T(r0,r1,r2,r3,a) \
    asm volatile("ldmatrix.sync.aligned.m8n8.x4.trans.shared.b16 {%0,%1,%2,%3}, [%4];" \
        : "=r"(r0), "=r"(r1), "=r"(r2), "=r"(r3) : "r"(a))

#define MMA_BF16(c, a, b0, b1) \
    asm volatile("mma.sync.aligned.m16n8k16.row.col.f32.bf16.bf16.f32 " \
        "{%0,%1,%2,%3}, {%4,%5,%6,%7}, {%8,%9}, {%0,%1,%2,%3};" \
        : "+f"((c)[0]), "+f"((c)[1]), "+f"((c)[2]), "+f"((c)[3]) \
        : "r"((a)[0]), "r"((a)[1]), "r"((a)[2]), "r"((a)[3]), "r"(b0), "r"(b1))

__device__ __forceinline__ uint32_t pack_bf2(__nv_bfloat16 a, __nv_bfloat16 b) {
    __nv_bfloat162 t; t.x = a; t.y = b;
    return *(uint32_t*)&t;
}
__device__ __forceinline__ uint32_t pack_hi(float a, float b) {
    return pack_bf2(__float2bfloat16(a), __float2bfloat16(b));
}
__device__ __forceinline__ uint32_t pack_lo(float a, float b) {
    __nv_bfloat16 ha = __float2bfloat16(a), hb = __float2bfloat16(b);
    return pack_bf2(__float2bfloat16(a - __bfloat162float(ha)),
                    __float2bfloat16(b - __bfloat162float(hb)));
}

// ================= weight transpose: in[R,C] -> out[C,R] =================
__global__ void __launch_bounds__(256) transpose_kernel(const float* __restrict__ in,
                                                        float* __restrict__ out, int R, int C)
{
    __shared__ float tile[32][33];
    int tx = threadIdx.x, ty = threadIdx.y;
    int x = blockIdx.x * 32 + tx;
    int y0 = blockIdx.y * 32;
#pragma unroll
    for (int i = ty; i < 32; i += 8)
        tile[i][tx] = in[(size_t)(y0 + i) * C + x];
    __syncthreads();
    int xo = y0 + tx;
    int y1 = blockIdx.x * 32;
#pragma unroll
    for (int i = ty; i < 32; i += 8)
        out[(size_t)(y1 + i) * R + xo] = tile[tx][i];
}

// ================= layernorm =================
__global__ void __launch_bounds__(256) ln_kernel(const float* __restrict__ in,
                                                 const float* __restrict__ gamma,
                                                 const float* __restrict__ beta,
                                                 float* __restrict__ out)
{
    int row = blockIdx.x;
    const float* x = in + (size_t)row * D_MODEL;
    int t = threadIdx.x;
    float v[4];
    float s = 0.f;
#pragma unroll
    for (int i = 0; i < 4; i++) { v[i] = x[i*256 + t]; s += v[i]; }

    __shared__ float red[8];
    __shared__ float bcast;
#pragma unroll
    for (int o = 16; o > 0; o >>= 1) s += __shfl_xor_sync(0xffffffffu, s, o);
    if ((t & 31) == 0) red[t >> 5] = s;
    __syncthreads();
    if (t < 32) {
        float r = (t < 8) ? red[t] : 0.f;
#pragma unroll
        for (int o = 4; o > 0; o >>= 1) r += __shfl_xor_sync(0xffffffffu, r, o);
        if (t == 0) bcast = r;
    }
    __syncthreads();
    float mean = bcast * (1.f / D_MODEL);

    float s2 = 0.f;
#pragma unroll
    for (int i = 0; i < 4; i++) { float d = v[i] - mean; s2 += d*d; }
#pragma unroll
    for (int o = 16; o > 0; o >>= 1) s2 += __shfl_xor_sync(0xffffffffu, s2, o);
    __syncthreads();
    if ((t & 31) == 0) red[t >> 5] = s2;
    __syncthreads();
    if (t < 32) {
        float r = (t < 8) ? red[t] : 0.f;
#pragma unroll
        for (int o = 4; o > 0; o >>= 1) r += __shfl_xor_sync(0xffffffffu, r, o);
        if (t == 0) bcast = r;
    }
    __syncthreads();
    float rstd = rsqrtf(bcast * (1.f / D_MODEL) + 1e-5f);

#pragma unroll
    for (int i = 0; i < 4; i++) {
        int d = i*256 + t;
        out[(size_t)row * D_MODEL + d] = gamma[d] * (v[i] - mean) * rstd + beta[d];
    }
}

// ================= split-bf16 mma.sync GEMM =================
#define ROW_BYTES  80
#define MAT_BYTES  (128*ROW_BYTES)      // 10240
#define STAGE_BYTES (4*MAT_BYTES)       // 40960
#define GEMM_SMEM  (2*STAGE_BYTES)      // 81920

template<int EPI>   // 0=none, 1=bias+res, 2=bias+gelu
__global__ void __launch_bounds__(256) gemm_mma(
    const float* __restrict__ A, const float* __restrict__ Bt,
    const float* __restrict__ bias, const float* __restrict__ res,
    float* __restrict__ C, int M, int N, int K)
{
    extern __shared__ char dynsm[];
    uint32_t sbase = smem_u32(dynsm);

    int t = threadIdx.x;
    int lane = t & 31, wid = t >> 5;
    int warp_m = wid & 3;
    int warp_n = wid >> 2;
    int m0 = blockIdx.y * 128, n0 = blockIdx.x * 128;
    const int NC = K >> 5;

    const float* Ap = A  + (size_t)m0 * K;
    const float* Bp = Bt + (size_t)n0 * K;

    int lrow  = t >> 3;
    int lcol4 = (t & 7) * 4;

    float acc[2][8][4];
#pragma unroll
    for (int mt = 0; mt < 2; mt++)
#pragma unroll
        for (int nt = 0; nt < 8; nt++)
#pragma unroll
            for (int r = 0; r < 4; r++) acc[mt][nt][r] = 0.f;

    auto sts_pair = [&](uint32_t mat_base, int row, int col4, float4 v) {
        uint32_t ah = mat_base + (uint32_t)(row * ROW_BYTES + col4 * 2);
        asm volatile("st.shared.v2.b32 [%0], {%1, %2};" :: "r"(ah),
                     "r"(pack_hi(v.x, v.y)), "r"(pack_hi(v.z, v.w)) : "memory");
        asm volatile("st.shared.v2.b32 [%0], {%1, %2};" :: "r"(ah + MAT_BYTES),
                     "r"(pack_lo(v.x, v.y)), "r"(pack_lo(v.z, v.w)) : "memory");
    };

    auto load_chunk_direct = [&](int k0, int st) {
        uint32_t stb = sbase + (uint32_t)st * STAGE_BYTES;
#pragma unroll
        for (int i = 0; i < 4; i++) {
            int row = lrow + i * 32;
            float4 a4 = *(const float4*)(Ap + (size_t)row * K + k0 + lcol4);
            sts_pair(stb, row, lcol4, a4);
            float4 b4 = *(const float4*)(Bp + (size_t)row * K + k0 + lcol4);
            sts_pair(stb + 2*MAT_BYTES, row, lcol4, b4);
        }
    };

    auto compute_stage = [&](int st) {
        uint32_t stb = sbase + (uint32_t)st * STAGE_BYTES;
        uint32_t ah_base = stb;
        uint32_t bh_base = stb + 2*MAT_BYTES;
#pragma unroll
        for (int ks = 0; ks < 2; ks++) {
            uint32_t afh[2][4], afl[2][4];
#pragma unroll
            for (int mt = 0; mt < 2; mt++) {
                int row = warp_m * 32 + mt * 16 + (lane & 15);
                int kcol = ks * 16 + (lane >> 4) * 8;
                uint32_t addr = ah_base + (uint32_t)(row * ROW_BYTES + kcol * 2);
                LDSM_X4(afh[mt][0], afh[mt][1], afh[mt][2], afh[mt][3], addr);
                LDSM_X4(afl[mt][0], afl[mt][1], afl[mt][2], afl[mt][3], addr + MAT_BYTES);
            }
#pragma unroll
            for (int np = 0; np < 4; np++) {
                int nrow = warp_n * 64 + np * 16 + (lane & 7) + ((lane >> 4) << 3);
                int kcol = ks * 16 + ((lane >> 3) & 1) * 8;
                uint32_t addr = bh_base + (uint32_t)(nrow * ROW_BYTES + kcol * 2);
                uint32_t bfh[4], bfl[4];
                LDSM_X4(bfh[0], bfh[1], bfh[2], bfh[3], addr);
                LDSM_X4(bfl[0], bfl[1], bfl[2], bfl[3], addr + MAT_BYTES);
#pragma unroll
                for (int mt = 0; mt < 2; mt++) {
                    int nt0 = np * 2;
                    MMA_BF16(acc[mt][nt0],   afh[mt], bfh[0], bfh[1]);
                    MMA_BF16(acc[mt][nt0+1], afh[mt], bfh[2], bfh[3]);
                    MMA_BF16(acc[mt][nt0],   afh[mt], bfl[0], bfl[1]);
                    MMA_BF16(acc[mt][nt0+1], afh[mt], bfl[2], bfl[3]);
                    MMA_BF16(acc[mt][nt0],   afl[mt], bfh[0], bfh[1]);
                    MMA_BF16(acc[mt][nt0+1], afl[mt], bfh[2], bfh[3]);
                }
            }
        }
    };

    load_chunk_direct(0, 0);
    __syncthreads();

    for (int c = 0; c < NC; c++) {
        int st = c & 1;
        bool has_next = (c + 1 < NC);
        float4 abuf[4], bbuf[4];
        if (has_next) {
            int k0 = (c + 1) * 32;
#pragma unroll
            for (int i = 0; i < 4; i++) {
                int row = lrow + i * 32;
                abuf[i] = *(const float4*)(Ap + (size_t)row * K + k0 + lcol4);
                bbuf[i] = *(const float4*)(Bp + (size_t)row * K + k0 + lcol4);
            }
        }
        compute_stage(st);
        if (has_next) {
            uint32_t stb = sbase + (uint32_t)(1 - st) * STAGE_BYTES;
#pragma unroll
            for (int i = 0; i < 4; i++) {
                int row = lrow + i * 32;
                sts_pair(stb, row, lcol4, abuf[i]);
                sts_pair(stb + 2*MAT_BYTES, row, lcol4, bbuf[i]);
            }
        }
        __syncthreads();
    }

    int g   = lane >> 2;
    int tig = lane & 3;
#pragma unroll
    for (int mt = 0; mt < 2; mt++) {
#pragma unroll
        for (int nt = 0; nt < 8; nt++) {
            int col = n0 + warp_n * 64 + nt * 8 + 2 * tig;
            int row0 = m0 + warp_m * 32 + mt * 16 + g;
            int row1 = row0 + 8;
            float v00 = acc[mt][nt][0], v01 = acc[mt][nt][1];
            float v10 = acc[mt][nt][2], v11 = acc[mt][nt][3];
            if (EPI != 0) {
                float b0 = bias[col], b1 = bias[col + 1];
                v00 += b0; v01 += b1; v10 += b0; v11 += b1;
            }
            if (EPI == 2) {
                float vv[4] = {v00, v01, v10, v11};
#pragma unroll
                for (int q = 0; q < 4; q++) {
                    float xx = vv[q];
                    float u = 0.7978845608028654f * (xx + 0.044715f * xx * xx * xx);
                    vv[q] = 0.5f * xx * (1.f + tanhf(u));
                }
                v00 = vv[0]; v01 = vv[1]; v10 = vv[2]; v11 = vv[3];
            }
            if (EPI == 1) {
                float2 r0 = *(const float2*)(res + (size_t)row0 * N + col);
                float2 r1 = *(const float2*)(res + (size_t)row1 * N + col);
                v00 += r0.x; v01 += r0.y; v10 += r1.x; v11 += r1.y;
            }
            *(float2*)(C + (size_t)row0 * N + col) = make_float2(v00, v01);
            *(float2*)(C + (size_t)row1 * N + col) = make_float2(v10, v11);
        }
    }
}

// ================= tensor-core flash attention (split-bf16) =================
// CTA: 128 queries x full head; k-tiles of 64. 8 warps x 16 q-rows.
// smem rows: 64 halves @ stride 144B (conflict-free ldmatrix).
#define AST 144
#define AQ_MAT (128*AST)     // 18432
#define AK_MAT (64*AST)      // 9216
// layout: Qh | Ql | Kh | Kl | Vh | Vl
#define ATT_SMEM (2*AQ_MAT + 4*AK_MAT)   // 73728

__global__ void __launch_bounds__(256) attn_mma(
    const float* __restrict__ QKV, float* __restrict__ O)
{
    extern __shared__ char asmem[];
    uint32_t sb = smem_u32(asmem);
    const uint32_t QH = sb, QL = sb + AQ_MAT;
    const uint32_t KH = QL + AQ_MAT, KL = KH + AK_MAT;
    const uint32_t VH = KL + AK_MAT, VL = VH + AK_MAT;

    int t = threadIdx.x, lane = t & 31, wid = t >> 5;
    int qt = blockIdx.x, bh = blockIdx.y;
    int b = bh >> 4, h = bh & 15;
    int q0 = qt * 128;

    const float* base = QKV + (size_t)b * SEQ * QKV_W + h * HDIM;
    const float* Qg = base;
    const float* Kg = base + D_MODEL;
    const float* Vg = base + 2 * D_MODEL;

    // ---- load Q tile (128 x 64) as hi/lo ----
    for (int idx = t; idx < 2048; idx += 256) {
        int r = idx >> 4, c4 = (idx & 15) * 4;
        float4 v = *(const float4*)(Qg + (size_t)(q0 + r) * QKV_W + c4);
        uint32_t ad = QH + (uint32_t)(r * AST + c4 * 2);
        asm volatile("st.shared.v2.b32 [%0], {%1, %2};" :: "r"(ad),
                     "r"(pack_hi(v.x, v.y)), "r"(pack_hi(v.z, v.w)) : "memory");
        asm volatile("st.shared.v2.b32 [%0], {%1, %2};" :: "r"(ad + AQ_MAT),
                     "r"(pack_lo(v.x, v.y)), "r"(pack_lo(v.z, v.w)) : "memory");
    }
    __syncthreads();

    // ---- preload Q fragments (4 k-steps x hi/lo) ----
    uint32_t qfh[4][4], qfl[4][4];
#pragma unroll
    for (int ks = 0; ks < 4; ks++) {
        int row = wid * 16 + (lane & 15);
        int kcol = ks * 16 + (lane >> 4) * 8;
        uint32_t ad = QH + (uint32_t)(row * AST + kcol * 2);
        LDSM_X4(qfh[ks][0], qfh[ks][1], qfh[ks][2], qfh[ks][3], ad);
        LDSM_X4(qfl[ks][0], qfl[ks][1], qfl[ks][2], qfl[ks][3], ad + AQ_MAT);
    }

    float oacc[8][4];
#pragma unroll
    for (int nt = 0; nt < 8; nt++)
#pragma unroll
        for (int e = 0; e < 4; e++) oacc[nt][e] = 0.f;
    float mrow[2] = {-1e30f, -1e30f};
    float lrow[2] = {0.f, 0.f};

    int qmax = q0 + wid * 16 + 15;
    int NK = qt * 2 + 2;
    int qrow0 = q0 + wid * 16 + (lane >> 2);
    int lj = 2 * (lane & 3);

    for (int kt = 0; kt < NK; kt++) {
        __syncthreads();   // previous K/V consumption done
        // load K/V tile (64 x 64) hi/lo
        for (int idx = t; idx < 1024; idx += 256) {
            int r = idx >> 4, c4 = (idx & 15) * 4;
            size_t grow = (size_t)(kt * 64 + r) * QKV_W + c4;
            uint32_t ad = (uint32_t)(r * AST + c4 * 2);
            float4 kv = *(const float4*)(Kg + grow);
            asm volatile("st.shared.v2.b32 [%0], {%1, %2};" :: "r"(KH + ad),
                         "r"(pack_hi(kv.x, kv.y)), "r"(pack_hi(kv.z, kv.w)) : "memory");
            asm volatile("st.shared.v2.b32 [%0], {%1, %2};" :: "r"(KL + ad),
                         "r"(pack_lo(kv.x, kv.y)), "r"(pack_lo(kv.z, kv.w)) : "memory");
            float4 vv = *(const float4*)(Vg + grow);
            asm volatile("st.shared.v2.b32 [%0], {%1, %2};" :: "r"(VH + ad),
                         "r"(pack_hi(vv.x, vv.y)), "r"(pack_hi(vv.z, vv.w)) : "memory");
            asm volatile("st.shared.v2.b32 [%0], {%1, %2};" :: "r"(VL + ad),
                         "r"(pack_lo(vv.x, vv.y)), "r"(pack_lo(vv.z, vv.w)) : "memory");
        }
        __syncthreads();
        if (kt * 64 > qmax) continue;    // this warp's rows all precede the tile

        // ---- S = Q K^T ----
        float sacc[8][4];
#pragma unroll
        for (int nt = 0; nt < 8; nt++)
#pragma unroll
            for (int e = 0; e < 4; e++) sacc[nt][e] = 0.f;
#pragma unroll
        for (int ks = 0; ks < 4; ks++) {
#pragma unroll
            for (int np = 0; np < 4; np++) {
                int nrow = np * 16 + (lane & 7) + ((lane >> 4) << 3);
                int kcol = ks * 16 + ((lane >> 3) & 1) * 8;
                uint32_t ad = KH + (uint32_t)(nrow * AST + kcol * 2);
                uint32_t bfh[4], bfl[4];
                LDSM_X4(bfh[0], bfh[1], bfh[2], bfh[3], ad);
                LDSM_X4(bfl[0], bfl[1], bfl[2], bfl[3], ad + AK_MAT);
                int nt0 = np * 2;
                MMA_BF16(sacc[nt0],   qfh[ks], bfh[0], bfh[1]);
                MMA_BF16(sacc[nt0+1], qfh[ks], bfh[2], bfh[3]);
                MMA_BF16(sacc[nt0],   qfh[ks], bfl[0], bfl[1]);
                MMA_BF16(sacc[nt0+1], qfh[ks], bfl[2], bfl[3]);
                MMA_BF16(sacc[nt0],   qfl[ks], bfh[0], bfh[1]);
                MMA_BF16(sacc[nt0+1], qfl[ks], bfh[2], bfh[3]);
            }
        }

        // ---- scale + causal mask ----
        bool maskt = (kt >= NK - 2);
#pragma unroll
        for (int nt = 0; nt < 8; nt++) {
            int kgb = kt * 64 + nt * 8 + lj;
#pragma unroll
            for (int e = 0; e < 4; e++) {
                float s = sacc[nt][e] * 0.125f;
                if (maskt) {
                    int kg = kgb + (e & 1);
                    int qg = qrow0 + (e >> 1) * 8;
                    if (kg > qg) s = -1e30f;
                }
                sacc[nt][e] = s;
            }
        }

        // ---- online softmax ----
        float tm0 = -1e30f, tm1 = -1e30f;
#pragma unroll
        for (int nt = 0; nt < 8; nt++) {
            tm0 = fmaxf(tm0, fmaxf(sacc[nt][0], sacc[nt][1]));
            tm1 = fmaxf(tm1, fmaxf(sacc[nt][2], sacc[nt][3]));
        }
        tm0 = fmaxf(tm0, __shfl_xor_sync(0xffffffffu, tm0, 1));
        tm0 = fmaxf(tm0, __shfl_xor_sync(0xffffffffu, tm0, 2));
        tm1 = fmaxf(tm1, __shfl_xor_sync(0xffffffffu, tm1, 1));
        tm1 = fmaxf(tm1, __shfl_xor_sync(0xffffffffu, tm1, 2));
        float mn0 = fmaxf(mrow[0], tm0), mn1 = fmaxf(mrow[1], tm1);
        float al0 = __expf(mrow[0] - mn0), al1 = __expf(mrow[1] - mn1);
        mrow[0] = mn0; mrow[1] = mn1;

        float rs0 = 0.f, rs1 = 0.f;
#pragma unroll
        for (int nt = 0; nt < 8; nt++) {
            float p0 = __expf(sacc[nt][0] - mn0);
            float p1 = __expf(sacc[nt][1] - mn0);
            float p2 = __expf(sacc[nt][2] - mn1);
            float p3 = __expf(sacc[nt][3] - mn1);
            sacc[nt][0] = p0; sacc[nt][1] = p1; sacc[nt][2] = p2; sacc[nt][3] = p3;
            rs0 += p0 + p1; rs1 += p2 + p3;
        }
        rs0 += __shfl_xor_sync(0xffffffffu, rs0, 1);
        rs0 += __shfl_xor_sync(0xffffffffu, rs0, 2);
        rs1 += __shfl_xor_sync(0xffffffffu, rs1, 1);
        rs1 += __shfl_xor_sync(0xffffffffu, rs1, 2);
        lrow[0] = lrow[0] * al0 + rs0;
        lrow[1] = lrow[1] * al1 + rs1;
#pragma unroll
        for (int nt = 0; nt < 8; nt++) {
            oacc[nt][0] *= al0; oacc[nt][1] *= al0;
            oacc[nt][2] *= al1; oacc[nt][3] *= al1;
        }

        // ---- O += P V : P fragments straight from registers ----
#pragma unroll
        for (int kt2 = 0; kt2 < 4; kt2++) {
            uint32_t aPh[4], aPl[4];
            int n0i = 2 * kt2, n1i = 2 * kt2 + 1;
            aPh[0] = pack_hi(sacc[n0i][0], sacc[n0i][1]);
            aPh[1] = pack_hi(sacc[n0i][2], sacc[n0i][3]);
            aPh[2] = pack_hi(sacc[n1i][0], sacc[n1i][1]);
            aPh[3] = pack_hi(sacc[n1i][2], sacc[n1i][3]);
            aPl[0] = pack_lo(sacc[n0i][0], sacc[n0i][1]);
            aPl[1] = pack_lo(sacc[n0i][2], sacc[n0i][3]);
            aPl[2] = pack_lo(sacc[n1i][0], sacc[n1i][1]);
            aPl[3] = pack_lo(sacc[n1i][2], sacc[n1i][3]);
#pragma unroll
            for (int dp = 0; dp < 4; dp++) {
                int krow = kt2 * 16 + ((lane >> 3) & 1) * 8 + (lane & 7);
                int dbyte = dp * 32 + (lane >> 4) * 16;
                uint32_t ad = VH + (uint32_t)(krow * AST + dbyte);
                uint32_t vfh[4], vfl[4];
                LDSM_X4_T(vfh[0], vfh[1], vfh[2], vfh[3], ad);
                LDSM_X4_T(vfl[0], vfl[1], vfl[2], vfl[3], ad + AK_MAT);
                MMA_BF16(oacc[2*dp],   aPh, vfh[0], vfh[1]);
                MMA_BF16(oacc[2*dp+1], aPh, vfh[2], vfh[3]);
                MMA_BF16(oacc[2*dp],   aPh, vfl[0], vfl[1]);
                MMA_BF16(oacc[2*dp+1], aPh, vfl[2], vfl[3]);
                MMA_BF16(oacc[2*dp],   aPl, vfh[0], vfh[1]);
                MMA_BF16(oacc[2*dp+1], aPl, vfh[2], vfh[3]);
            }
        }
    }

    // ---- normalize + write ----
    float inv0 = 1.f / lrow[0], inv1 = 1.f / lrow[1];
    size_t ob = ((size_t)b * SEQ + qrow0) * D_MODEL + h * HDIM;
#pragma unroll
    for (int nt = 0; nt < 8; nt++) {
        int cb = nt * 8 + lj;
        *(float2*)(O + ob + cb) = make_float2(oacc[nt][0] * inv0, oacc[nt][1] * inv0);
        *(float2*)(O + ob + 8 * D_MODEL + cb) = make_float2(oacc[nt][2] * inv1, oacc[nt][3] * inv1);
    }
}

// ================= launch =================
extern "C" void kernel_launch(void* const* d_in, const int* in_sizes, int n_in,
                              void* d_out, int out_size)
{
    (void)in_sizes; (void)n_in; (void)out_size;
    const float* x  = (const float*)d_in[0];
    const float* Wq = (const float*)d_in[1];
    const float* Wk = (const float*)d_in[2];
    const float* Wv = (const float*)d_in[3];
    const float* Wo = (const float*)d_in[4];
    const float* bo = (const float*)d_in[5];
    const float* W1 = (const float*)d_in[6];
    const float* b1 = (const float*)d_in[7];
    const float* W2 = (const float*)d_in[8];
    const float* b2 = (const float*)d_in[9];
    const float* g1 = (const float*)d_in[10];
    const float* s1 = (const float*)d_in[11];
    const float* g2 = (const float*)d_in[12];
    const float* s2 = (const float*)d_in[13];
    float* out = (float*)d_out;

    float *ln, *qkv, *ctx, *h, *f1, *wqkvT, *woT, *w1T, *w2T;
    cudaGetSymbolAddress((void**)&ln,    g_ln);
    cudaGetSymbolAddress((void**)&qkv,   g_qkv);
    cudaGetSymbolAddress((void**)&ctx,   g_ctx);
    cudaGetSymbolAddress((void**)&h,     g_h);
    cudaGetSymbolAddress((void**)&f1,    g_f1);
    cudaGetSymbolAddress((void**)&wqkvT, g_wqkvT);
    cudaGetSymbolAddress((void**)&woT,   g_woT);
    cudaGetSymbolAddress((void**)&w1T,   g_w1T);
    cudaGetSymbolAddress((void**)&w2T,   g_w2T);

    cudaFuncSetAttribute(gemm_mma<0>, cudaFuncAttributeMaxDynamicSharedMemorySize, GEMM_SMEM);
    cudaFuncSetAttribute(gemm_mma<1>, cudaFuncAttributeMaxDynamicSharedMemorySize, GEMM_SMEM);
    cudaFuncSetAttribute(gemm_mma<2>, cudaFuncAttributeMaxDynamicSharedMemorySize, GEMM_SMEM);
    cudaFuncSetAttribute(attn_mma, cudaFuncAttributeMaxDynamicSharedMemorySize, ATT_SMEM);

    dim3 tb(32, 8);
    transpose_kernel<<<dim3(D_MODEL/32, D_MODEL/32), tb>>>(Wq, wqkvT,                        D_MODEL, D_MODEL);
    transpose_kernel<<<dim3(D_MODEL/32, D_MODEL/32), tb>>>(Wk, wqkvT + 1024*(size_t)D_MODEL, D_MODEL, D_MODEL);
    transpose_kernel<<<dim3(D_MODEL/32, D_MODEL/32), tb>>>(Wv, wqkvT + 2048*(size_t)D_MODEL, D_MODEL, D_MODEL);
    transpose_kernel<<<dim3(D_MODEL/32, D_MODEL/32), tb>>>(Wo, woT, D_MODEL, D_MODEL);
    transpose_kernel<<<dim3(DFF/32,     D_MODEL/32), tb>>>(W1, w1T, D_MODEL, DFF);
    transpose_kernel<<<dim3(D_MODEL/32, DFF/32),     tb>>>(W2, w2T, DFF, D_MODEL);

    // 1. ln1 = LN(x)
    ln_kernel<<<NTOK, 256>>>(x, g1, s1, ln);
    // 2. qkv = ln1 @ [Wq|Wk|Wv]
    gemm_mma<0><<<dim3(QKV_W/128, NTOK/128), 256, GEMM_SMEM>>>(ln, wqkvT, nullptr, nullptr, qkv, NTOK, QKV_W, D_MODEL);
    // 3. causal attention (tensor core)
    attn_mma<<<dim3(SEQ/128, BATCH*NHEADS), 256, ATT_SMEM>>>(qkv, ctx);
    // 4. h = x + ctx @ Wo + bo
    gemm_mma<1><<<dim3(D_MODEL/128, NTOK/128), 256, GEMM_SMEM>>>(ctx, woT, bo, x, h, NTOK, D_MODEL, D_MODEL);
    // 5. ln2 = LN(h)
    ln_kernel<<<NTOK, 256>>>(h, g2, s2, ln);
    // 6. f1 = gelu(ln2 @ W1 + b1)
    gemm_mma<2><<<dim3(DFF/128, NTOK/128), 256, GEMM_SMEM>>>(ln, w1T, b1, nullptr, f1, NTOK, DFF, D_MODEL);
    // 7. out = h + f1 @ W2 + b2
    gemm_mma<1><<<dim3(D_MODEL/128, NTOK/128), 256, GEMM_SMEM>>>(f1, w2T, b2, h, out, NTOK, D_MODEL, DFF);
}